// round 15
// baseline (speedup 1.0000x reference)
#include <cuda_runtime.h>

#define BB 2
#define CC 64
#define HH 96
#define WW 192
#define DD 48
#define GG 8
#define HW (HH*WW)
#define NCH 4

// ---------------- scratch (static device globals; no allocation) ----------------
__device__ float g_fln[BB*GG*HW*8];              // [b][g][h][w][c]
__device__ float g_frn[BB*GG*HW*8];              // [b][g][h][w][c]
__device__ float g_base[(size_t)BB*DD*GG*HW];    // [b][d][g][h][w]
__device__ float g_sw2[3*BB*HW];                 // [s][b][hw]
__device__ float g_wpack2[5184];                 // [s][kd][kh][gi][kw][g] (un-dup)
__device__ float g_w1pack[65*9*32];              // [ic][tap][oc]
__device__ float g_pmid[(size_t)NCH*BB*32*HW];   // partial conv32 outputs
__device__ float g_bnscale[32];
__device__ float g_bnbias[32];

// ---------------- f32x2 helpers ----------------
typedef unsigned long long ull;
__device__ __forceinline__ ull pk2(float lo, float hi) {
    ull r;
    asm("mov.b64 %0, {%1, %2};" : "=l"(r) : "f"(lo), "f"(hi));
    return r;
}
__device__ __forceinline__ void upk2(float& lo, float& hi, ull v) {
    asm("mov.b64 {%0, %1}, %2;" : "=f"(lo), "=f"(hi) : "l"(v));
}
__device__ __forceinline__ void fma2(ull& d, ull a, ull b) {
    asm("fma.rn.f32x2 %0, %1, %2, %0;" : "+l"(d) : "l"(a), "l"(b));
}

// ---------------- K0: norm (blocks 0..1535) + weight prep (blocks 1536..1562) ----------------
__global__ void __launch_bounds__(192) k_norm_prep(
        const float* __restrict__ fl, const float* __restrict__ fr,
        const float* __restrict__ w_s, const float* __restrict__ w_m,
        const float* __restrict__ w_l, const float* __restrict__ w_pred1,
        const float* __restrict__ gamma, const float* __restrict__ beta,
        const float* __restrict__ mean, const float* __restrict__ var) {
    int blk = blockIdx.x;
    if (blk < 1536) {
        int idx = blk*192 + threadIdx.x;   // over BB*GG*HW exactly
        int pix = idx % HW;
        int bg  = idx / HW;
        const float* pl = fl + (size_t)bg*8*HW + pix;
        const float* pr = fr + (size_t)bg*8*HW + pix;
        float vl[8], vr[8];
        float sl = 0.f, sr = 0.f;
#pragma unroll
        for (int c = 0; c < 8; c++) {
            vl[c] = pl[c*HW]; sl += vl[c]*vl[c];
            vr[c] = pr[c*HW]; sr += vr[c]*vr[c];
        }
        float il = 1.0f / fmaxf(sqrtf(sl), 1e-12f);
        float ir = 1.0f / fmaxf(sqrtf(sr), 1e-12f);
        float* ol = g_fln + (size_t)idx*8;
        float* orr = g_frn + (size_t)idx*8;
#pragma unroll
        for (int c = 0; c < 8; c++) { ol[c] = vl[c]*il; orr[c] = vr[c]*ir; }
    } else {
        int tid = (blk - 1536)*192 + threadIdx.x;   // 0..5183
        // un-dup'd 3d conv weights: dst [s][kd][kh][gi][kw][g]
        {
            int i = tid;
            int g  = i & 7;
            int kw = (i >> 3) % 3;
            int gi = (i / 24) & 7;
            int kh = (i / 192) % 3;
            int kd = (i / 576) % 3;
            int s  = i / 1728;
            const float* w = (s == 0) ? w_s : ((s == 1) ? w_m : w_l);
            g_wpack2[i] = w[(g*8 + gi)*27 + (kd*3 + kh)*3 + kw];
        }
        // pred1 weights: src (oc, ic, kh, kw) -> dst [ic][t][oc]
        for (int i = tid; i < 65*9*32; i += 5184) {
            int oc = i & 31;
            int t  = (i >> 5) % 9;
            int ic = i / 288;
            g_w1pack[i] = w_pred1[(oc*65 + ic)*9 + t];
        }
        if (tid < 32) {
            float sc = gamma[tid] * rsqrtf(var[tid] + 1e-5f);
            g_bnscale[tid] = sc;
            g_bnbias[tid]  = beta[tid] - mean[tid]*sc;
        }
    }
}

// ---------------- K1: pred_part (blocks 0..767) + corr (blocks 768..2303) ----------------
__global__ void __launch_bounds__(192) k_corr_pred(const float* __restrict__ feat_l,
                                                   const float* __restrict__ edge) {
    __shared__ __align__(16) float sW[17*9*32];
    int blk = blockIdx.x;
    int tid = threadIdx.x;

    if (blk < BB*HH*NCH) {
        // ---- predictor conv partials ----
        int h = blk % HH;
        int t2 = blk / HH;
        int chunk = t2 % NCH;
        int b = t2 / NCH;
        int c0 = (chunk == 0) ? 0 : (17 + 16*(chunk - 1));
        int cn = (chunk == 0) ? 17 : 16;
        for (int i = tid; i < cn*288; i += 192) sW[i] = g_w1pack[c0*288 + i];
        __syncthreads();

        int w = tid;
        ull acc[16];
#pragma unroll
        for (int k = 0; k < 16; k++) acc[k] = 0ull;

        for (int ic2 = 0; ic2 < cn; ic2++) {
            int ic = c0 + ic2;
            const float* xin = (ic < 64) ? (feat_l + (size_t)(b*64 + ic)*HW)
                                         : (edge + (size_t)b*HW);
#pragma unroll
            for (int kh = 0; kh < 3; kh++) {
                int hh = h + kh - 1;
                if ((unsigned)hh >= HH) continue;
#pragma unroll
                for (int kw = 0; kw < 3; kw++) {
                    int ww = w + kw - 1;
                    if ((unsigned)ww >= WW) continue;
                    float xv = xin[hh*WW + ww];
                    ull xp = pk2(xv, xv);
                    const ulonglong2* wp = (const ulonglong2*)&sW[(ic2*9 + kh*3 + kw)*32];
#pragma unroll
                    for (int j = 0; j < 8; j++) {
                        ulonglong2 v = wp[j];
                        fma2(acc[2*j],   v.x, xp);
                        fma2(acc[2*j+1], v.y, xp);
                    }
                }
            }
        }
        float* op = g_pmid + (size_t)chunk*(BB*32*HW) + (size_t)(b*32)*HW + h*WW + w;
#pragma unroll
        for (int k = 0; k < 16; k++) {
            float lo, hi; upk2(lo, hi, acc[k]);
            op[(size_t)(2*k)*HW]   = lo;
            op[(size_t)(2*k+1)*HW] = hi;
        }
    } else {
        // ---- correlation volume ----
        int idx = (blk - BB*HH*NCH)*192 + tid;   // over BB*GG*HW exactly
        int w = idx % WW;
        int rest = idx / WW;
        int h = rest % HH;
        int bg = rest / HH;
        int g = bg & 7, b = bg >> 3;
        const float4* fl4 = (const float4*)(g_fln + (size_t)idx*8);
        float4 a0 = fl4[0], a1 = fl4[1];
        const float inv = 0.35355339059327373f;
        const float* frrow = g_frn + ((size_t)(bg*HH + h)*WW)*8;
        float* op = g_base + ((size_t)b*DD*GG + g)*HW + h*WW + w;
        for (int d = 0; d < DD; d++) {
            float val = 0.f;
            if (w >= d) {
                const float4* f4 = (const float4*)(frrow + (size_t)(w - d)*8);
                float4 b0 = f4[0], b1 = f4[1];
                val = (a0.x*b0.x + a0.y*b0.y + a0.z*b0.z + a0.w*b0.w +
                       a1.x*b1.x + a1.y*b1.y + a1.z*b1.z + a1.w*b1.w) * inv;
            }
            op[(size_t)d*GG*HW] = val;
        }
    }
}

// ---------------- K2: combine partials + BN + ReLU + 1x1 + softmax ----------------
__global__ void k_pred_fin(const float* __restrict__ w2, const float* __restrict__ b2,
                           const float* __restrict__ temp) {
    int idx = blockIdx.x * blockDim.x + threadIdx.x;
    if (idx >= BB*HW) return;
    int b = idx / HW;
    int pix = idx % HW;
    float l0 = b2[0], l1 = b2[1], l2 = b2[2];
    const float* base = g_pmid + (size_t)(b*32)*HW + pix;
#pragma unroll 4
    for (int o = 0; o < 32; o++) {
        float v = 0.f;
#pragma unroll
        for (int c = 0; c < NCH; c++)
            v += base[(size_t)c*(BB*32*HW) + (size_t)o*HW];
        v = fmaxf(v*g_bnscale[o] + g_bnbias[o], 0.f);
        l0 += __ldg(&w2[o])      * v;
        l1 += __ldg(&w2[32 + o]) * v;
        l2 += __ldg(&w2[64 + o]) * v;
    }
    float t = fmaxf(temp[0], 0.1f);
    l0 /= t; l1 /= t; l2 /= t;
    float m = fmaxf(l0, fmaxf(l1, l2));
    float e0 = expf(l0 - m), e1 = expf(l1 - m), e2 = expf(l2 - m);
    float r = 1.0f / (e0 + e1 + e2);
    g_sw2[0*BB*HW + idx] = e0*r;
    g_sw2[1*BB*HW + idx] = e1*r;
    g_sw2[2*BB*HW + idx] = e2*r;
}

// ---------------- K3: fused 3-scale dilated conv3d + blend + 1x1x1 ----------------
// 4 px/thread, g-pair accumulator lanes. Per gi: 6 LDS.128 (un-dup weights) +
// 3 LDG feed 48 fma2 (L1-instr per fma2 halved vs 2px version).
__global__ void __launch_bounds__(192) k_fuse(const float* __restrict__ wf,
                                              const float* __restrict__ bfin,
                                              float* __restrict__ out) {
    __shared__ __align__(16) float sWt[5184];    // 20.7 KB un-dup weights
    __shared__ __align__(16) float sWf[256];
    __shared__ float sBf[32];
    int tid = threadIdx.x;
    for (int i = tid; i < 5184; i += 192) sWt[i] = g_wpack2[i];
    for (int i = tid; i < 256; i += 192) sWf[i] = wf[i];
    if (tid < 32) sBf[tid] = bfin[tid];
    __syncthreads();

    int lw = tid % 48;
    int dz = tid / 48;          // 0..3
    int w0 = lw * 4;
    int h  = blockIdx.x % HH;
    int bd = blockIdx.x / HH;
    int d  = (bd % 12)*4 + dz;
    int b  = bd / 12;

    int pix0 = h*WW + w0;

    ull fu[4][4];               // [px][gpair]
#pragma unroll
    for (int p = 0; p < 4; p++)
#pragma unroll
        for (int g = 0; g < 4; g++) fu[p][g] = 0ull;

    const float* bb = g_base + (size_t)b*DD*GG*HW;

#pragma unroll
    for (int s = 0; s < 3; s++) {
        const int dil = 1 << s;
        bool aok = (w0 >= 4);          // left neighborhood exists (w0 > 0)
        bool cok = (w0 <= 184);        // right loads stay in-row
        ull acc[4][4];
#pragma unroll
        for (int p = 0; p < 4; p++)
#pragma unroll
            for (int g = 0; g < 4; g++) acc[p][g] = 0ull;

#pragma unroll 1
        for (int kd = 0; kd < 3; kd++) {
            int dd = d + (kd - 1)*dil;
            if ((unsigned)dd >= DD) continue;
#pragma unroll 1
            for (int kh = 0; kh < 3; kh++) {
                int hh = h + (kh - 1)*dil;
                if ((unsigned)hh >= HH) continue;
                const float* row = bb + (size_t)dd*GG*HW + hh*WW;
                const float* swrow = &sWt[((s*3 + kd)*3 + kh)*192];
#pragma unroll
                for (int gi = 0; gi < 8; gi++) {
                    const float* p = row + gi*HW;
                    float4 Bv = *(const float4*)(p + w0);   // w0 16B-aligned
                    // x[kw][px] tap values; m = splat
                    ull m0[4], m1[4], m2[4];
                    m1[0] = pk2(Bv.x, Bv.x); m1[1] = pk2(Bv.y, Bv.y);
                    m1[2] = pk2(Bv.z, Bv.z); m1[3] = pk2(Bv.w, Bv.w);
                    if (s == 0) {
                        float av = aok ? p[w0 - 1] : 0.f;
                        float cv = cok ? p[w0 + 4] : 0.f;
                        m0[0] = pk2(av, av); m0[1] = m1[0]; m0[2] = m1[1]; m0[3] = m1[2];
                        m2[0] = m1[1]; m2[1] = m1[2]; m2[2] = m1[3]; m2[3] = pk2(cv, cv);
                    } else if (s == 1) {
                        float a0 = 0.f, a1 = 0.f, c0 = 0.f, c1 = 0.f;
                        if (aok) { ull av = *(const ull*)(p + w0 - 2); upk2(a0, a1, av); }
                        if (cok) { ull cv = *(const ull*)(p + w0 + 4); upk2(c0, c1, cv); }
                        m0[0] = pk2(a0, a0); m0[1] = pk2(a1, a1); m0[2] = m1[0]; m0[3] = m1[1];
                        m2[0] = m1[2]; m2[1] = m1[3]; m2[2] = pk2(c0, c0); m2[3] = pk2(c1, c1);
                    } else {
                        float4 Av = make_float4(0.f,0.f,0.f,0.f), Cv = Av;
                        if (aok) Av = *(const float4*)(p + w0 - 4);
                        if (cok) Cv = *(const float4*)(p + w0 + 4);
                        m0[0] = pk2(Av.x, Av.x); m0[1] = pk2(Av.y, Av.y);
                        m0[2] = pk2(Av.z, Av.z); m0[3] = pk2(Av.w, Av.w);
                        m2[0] = pk2(Cv.x, Cv.x); m2[1] = pk2(Cv.y, Cv.y);
                        m2[2] = pk2(Cv.z, Cv.z); m2[3] = pk2(Cv.w, Cv.w);
                    }
                    const ulonglong2* wk = (const ulonglong2*)(swrow + gi*24);
                    {   // kw = 0
                        ulonglong2 wv0 = wk[0], wv1 = wk[1];
#pragma unroll
                        for (int px = 0; px < 4; px++) {
                            fma2(acc[px][0], wv0.x, m0[px]);
                            fma2(acc[px][1], wv0.y, m0[px]);
                            fma2(acc[px][2], wv1.x, m0[px]);
                            fma2(acc[px][3], wv1.y, m0[px]);
                        }
                    }
                    {   // kw = 1
                        ulonglong2 wv0 = wk[2], wv1 = wk[3];
#pragma unroll
                        for (int px = 0; px < 4; px++) {
                            fma2(acc[px][0], wv0.x, m1[px]);
                            fma2(acc[px][1], wv0.y, m1[px]);
                            fma2(acc[px][2], wv1.x, m1[px]);
                            fma2(acc[px][3], wv1.y, m1[px]);
                        }
                    }
                    {   // kw = 2
                        ulonglong2 wv0 = wk[4], wv1 = wk[5];
#pragma unroll
                        for (int px = 0; px < 4; px++) {
                            fma2(acc[px][0], wv0.x, m2[px]);
                            fma2(acc[px][1], wv0.y, m2[px]);
                            fma2(acc[px][2], wv1.x, m2[px]);
                            fma2(acc[px][3], wv1.y, m2[px]);
                        }
                    }
                }
            }
        }
        // blend this scale into fu: per-pixel softmax weight splat
        float4 sv = *(const float4*)(g_sw2 + (size_t)s*BB*HW + (size_t)b*HW + pix0);
        ull q[4] = { pk2(sv.x, sv.x), pk2(sv.y, sv.y), pk2(sv.z, sv.z), pk2(sv.w, sv.w) };
#pragma unroll
        for (int px = 0; px < 4; px++)
#pragma unroll
            for (int g = 0; g < 4; g++)
                fma2(fu[px][g], q[px], acc[px][g]);
    }

    // epilogue: 1x1x1 conv to 32 channels (un-dup weights, horizontal add)
    float* op = out + (((size_t)b*32)*DD + d)*HW + pix0;
#pragma unroll
    for (int o = 0; o < 32; o++) {
        const ulonglong2* wo = (const ulonglong2*)&sWf[o*8];
        ulonglong2 wv0 = wo[0], wv1 = wo[1];
        float bias = sBf[o];
        float res[4];
#pragma unroll
        for (int px = 0; px < 4; px++) {
            ull a = 0ull;
            fma2(a, wv0.x, fu[px][0]);
            fma2(a, wv0.y, fu[px][1]);
            fma2(a, wv1.x, fu[px][2]);
            fma2(a, wv1.y, fu[px][3]);
            float e0, e1; upk2(e0, e1, a);
            res[px] = bias + e0 + e1;
        }
        __stcs((float4*)(op + (size_t)o*DD*HW),
               make_float4(res[0], res[1], res[2], res[3]));
    }
}

// ---------------- launch ----------------
extern "C" void kernel_launch(void* const* d_in, const int* in_sizes, int n_in,
                              void* d_out, int out_size) {
    const float* feat_l  = (const float*)d_in[0];
    const float* feat_r  = (const float*)d_in[1];
    const float* edge    = (const float*)d_in[2];
    const float* w_pred1 = (const float*)d_in[3];
    const float* gamma   = (const float*)d_in[4];
    const float* beta    = (const float*)d_in[5];
    const float* mean    = (const float*)d_in[6];
    const float* var     = (const float*)d_in[7];
    const float* w_pred2 = (const float*)d_in[8];
    const float* b_pred2 = (const float*)d_in[9];
    const float* temp    = (const float*)d_in[10];
    const float* w_s     = (const float*)d_in[11];
    const float* w_m     = (const float*)d_in[12];
    const float* w_l     = (const float*)d_in[13];
    const float* w_final = (const float*)d_in[14];
    const float* b_final = (const float*)d_in[15];
    float* out = (float*)d_out;

    // launch idx 0: norm + weight prep
    k_norm_prep<<<1536 + 27, 192>>>(feat_l, feat_r, w_s, w_m, w_l, w_pred1,
                                    gamma, beta, mean, var);
    // launch idx 1: pred_part + corr
    k_corr_pred<<<BB*HH*NCH + 1536, 192>>>(feat_l, edge);
    // launch idx 2: softmax weights
    k_pred_fin<<<(BB*HW + 255)/256, 256>>>(w_pred2, b_pred2, temp);
    // launch idx 3: the big one (ncu capture lands here)
    k_fuse<<<BB*12*HH, 192>>>(w_final, b_final, out);
}